// round 6
// baseline (speedup 1.0000x reference)
#include <cuda_runtime.h>

#define SEQ   96
#define PRED  16
#define HID   64
#define FEAT  7
#define BPB   2               // batches per block
#define NBLK  256             // 512/2
#define NTHR  256
#define WIN   (SEQ + PRED)

typedef unsigned long long ull;

static __device__ __forceinline__ ull pack2(float a, float b){
    ull r; asm("mov.b64 %0, {%1, %2};" : "=l"(r) : "f"(a), "f"(b)); return r;
}
static __device__ __forceinline__ void unpack2(ull v, float &a, float &b){
    asm("mov.b64 {%0, %1}, %2;" : "=f"(a), "=f"(b) : "l"(v));
}
// d = a*b + d, packed f32x2 (Blackwell FFMA2), exact fp32 per lane
static __device__ __forceinline__ void ffma2(ull &d, ull a, ull b){
    asm("fma.rn.f32x2 %0, %1, %2, %0;" : "+l"(d) : "l"(a), "l"(b));
}

static __device__ __forceinline__ float sigmoid_fast(float x){
    float e = __expf(-x);
    return __fdividef(1.0f, 1.0f + e);
}
static __device__ __forceinline__ float tanhf_fast(float x){
    float e = __expf(-2.0f * x);
    return __fdividef(2.0f, 1.0f + e) - 1.0f;
}

__global__ void __launch_bounds__(NTHR, 2)
lstm_ar_kernel(const float* __restrict__ x,
               const float* __restrict__ W_ih,
               const float* __restrict__ W_hh,
               const float* __restrict__ b_ih,
               const float* __restrict__ b_hh,
               const float* __restrict__ fc_W,
               const float* __restrict__ fc_b,
               float* __restrict__ out)
{
    // sliding input window: [t][feat][b]
    __shared__ float sh_xw[WIN * FEAT * BPB];
    // hidden state, double-buffered: [buf][b*64+u]
    __shared__ float h_sh[2][BPB * HID];
    // kh=1 partials: [b][row]
    __shared__ float sp[BPB][256];
    // kh=0 other-batch pairs: sx[tl] = (rowA, rowB) partials of the non-owned batch
    __shared__ float2 sx[128];
    __shared__ float sh_fcW[FEAT * HID];
    __shared__ float sh_fcb[FEAT];

    const int tid = threadIdx.x;            // 0..255
    const int kh  = tid >> 7;               // K-half: cols [kh*32, kh*32+32)
    const int tl  = tid & 127;              // row selector
    const int r0  = tl;                     // row A: gate i (tl<64) or f (tl>=64)
    const int r1  = tl + 128;               // row B: gate g (tl<64) or o (tl>=64)
    const int b0  = blockIdx.x * BPB;

    // ---------------- one-time init ----------------
    for (int i = tid; i < SEQ * FEAT * BPB; i += NTHR){
        int b = i & 1;
        int q = i >> 1;
        int f = q % FEAT;
        int t = q / FEAT;
        sh_xw[(t * FEAT + f) * BPB + b] =
            x[(size_t)(b0 + b) * SEQ * FEAT + t * FEAT + f];
    }
    for (int i = tid; i < FEAT * HID; i += NTHR) sh_fcW[i] = fc_W[i];
    if (tid < FEAT) sh_fcb[tid] = fc_b[tid];
    {
        float* hz = &h_sh[0][0];
        for (int i = tid; i < 2 * BPB * HID; i += NTHR) hz[i] = 0.0f;
    }

    // W_hh slices: rows r0,r1, cols [kh*32, kh*32+32), natural column-pairs.
    ull whhA[16], whhB[16];
    {
        const ull* wa = reinterpret_cast<const ull*>(W_hh + (size_t)r0 * HID + kh * 32);
        const ull* wb = reinterpret_cast<const ull*>(W_hh + (size_t)r1 * HID + kh * 32);
        #pragma unroll
        for (int c = 0; c < 16; c++){ whhA[c] = wa[c]; whhB[c] = wb[c]; }
    }
    // x-projection weights (used by kh=0 only)
    float wihA[FEAT], wihB[FEAT];
    #pragma unroll
    for (int f = 0; f < FEAT; f++){
        wihA[f] = W_ih[r0 * FEAT + f];
        wihB[f] = W_ih[r1 * FEAT + f];
    }
    // bias seeded once (kh=0), lands in even lane of the f32x2 acc
    const ull seedA = (kh == 0) ? pack2(b_ih[r0] + b_hh[r0], 0.0f) : 0ull;
    const ull seedB = (kh == 0) ? pack2(b_ih[r1] + b_hh[r1], 0.0f) : 0ull;

    float c_reg = 0.0f;    // cell state: finisher (kh=0) thread owns (u = tl&63, b = tl>=64)
    int p = 0;

    __syncthreads();

    // ---------------- 16 AR iterations x 96 recurrent steps ----------------
    for (int k = 0; k < PRED; k++){
        for (int t = 0; t < SEQ; t++){
            // ---- partial dot: 2 rows x 2 batches over 32 cols ----
            ull aA0 = seedA, aA1 = seedA;
            ull aB0 = seedB, aB1 = seedB;
            const ulonglong2* h0 =
                reinterpret_cast<const ulonglong2*>(&h_sh[p][0]) + kh * 8;
            const ulonglong2* h1 =
                reinterpret_cast<const ulonglong2*>(&h_sh[p][HID]) + kh * 8;
            #pragma unroll
            for (int c = 0; c < 8; c++){
                ulonglong2 u0 = h0[c];     // cols 4c..4c+3 of this K-half, batch 0
                ulonglong2 u1 = h1[c];     // batch 1
                ffma2(aA0, u0.x, whhA[2*c]);
                ffma2(aA0, u0.y, whhA[2*c+1]);
                ffma2(aB0, u0.x, whhB[2*c]);
                ffma2(aB0, u0.y, whhB[2*c+1]);
                ffma2(aA1, u1.x, whhA[2*c]);
                ffma2(aA1, u1.y, whhA[2*c+1]);
                ffma2(aB1, u1.x, whhB[2*c]);
                ffma2(aB1, u1.y, whhB[2*c+1]);
            }
            float e, o;
            float vA0, vA1, vB0, vB1;
            unpack2(aA0, e, o); vA0 = e + o;
            unpack2(aA1, e, o); vA1 = e + o;
            unpack2(aB0, e, o); vB0 = e + o;
            unpack2(aB1, e, o); vB1 = e + o;

            if (kh == 0){
                // x-projection (once per row-batch)
                const float2* xp =
                    reinterpret_cast<const float2*>(&sh_xw[(k + t) * FEAT * BPB]);
                #pragma unroll
                for (int f = 0; f < FEAT; f++){
                    float2 xx = xp[f];
                    vA0 = fmaf(wihA[f], xx.x, vA0);
                    vA1 = fmaf(wihA[f], xx.y, vA1);
                    vB0 = fmaf(wihB[f], xx.x, vB0);
                    vB1 = fmaf(wihB[f], xx.y, vB1);
                }
                // publish the batch this thread does NOT finish
                sx[tl] = (tl < 64) ? make_float2(vA1, vB1)   // i,g partials, b=1
                                   : make_float2(vA0, vB0);  // f,o partials, b=0
            } else {
                // kh=1: publish all 4 partials, conflict-free [b][row]
                sp[0][r0] = vA0;
                sp[1][r0] = vA1;
                sp[0][r1] = vB0;
                sp[1][r1] = vB1;
            }
            __syncthreads();

            // ---- finishers: kh=0 threads, one (unit, batch) each ----
            if (kh == 0){
                const int uu = tl & 63;
                float ip, fp, gp, op;
                if (tl < 64){   // batch 0: own regs hold i,g
                    ip = vA0 + sp[0][uu];
                    gp = vB0 + sp[0][128 + uu];
                    float2 fo = sx[64 + uu];
                    fp = fo.x + sp[0][64 + uu];
                    op = fo.y + sp[0][192 + uu];
                } else {        // batch 1: own regs hold f,o
                    fp = vA1 + sp[1][64 + uu];
                    op = vB1 + sp[1][192 + uu];
                    float2 ig = sx[uu];
                    ip = ig.x + sp[1][uu];
                    gp = ig.y + sp[1][128 + uu];
                }
                float gi = sigmoid_fast(ip);
                float gf = sigmoid_fast(fp);
                float gg = tanhf_fast(gp);
                float go = sigmoid_fast(op);
                c_reg = fmaf(gf, c_reg, gi * gg);
                const int b = (tl >= 64);
                h_sh[p ^ 1][b * HID + uu] = go * tanhf_fast(c_reg);
            }
            __syncthreads();
            p ^= 1;
        }

        // ---- fc head: pred = h @ fc_W^T + fc_b; append to window; emit ----
        if (tid < FEAT * BPB){
            int b  = tid / FEAT;
            int o2 = tid - b * FEAT;
            float acc = sh_fcb[o2];
            #pragma unroll
            for (int jj = 0; jj < HID; jj++)
                acc += h_sh[p][b * HID + jj] * sh_fcW[o2 * HID + jj];
            out[(size_t)(b0 + b) * PRED * FEAT + k * FEAT + o2] = acc;
            sh_xw[((SEQ + k) * FEAT + o2) * BPB + b] = acc;
        }
        __syncthreads();
    }
}

extern "C" void kernel_launch(void* const* d_in, const int* in_sizes, int n_in,
                              void* d_out, int out_size)
{
    const float* x    = (const float*)d_in[0];
    const float* W_ih = (const float*)d_in[1];
    const float* W_hh = (const float*)d_in[2];
    const float* b_ih = (const float*)d_in[3];
    const float* b_hh = (const float*)d_in[4];
    const float* fc_W = (const float*)d_in[5];
    const float* fc_b = (const float*)d_in[6];
    float* out = (float*)d_out;

    lstm_ar_kernel<<<NBLK, NTHR>>>(x, W_ih, W_hh, b_ih, b_hh, fc_W, fc_b, out);
}

// round 7
// speedup vs baseline: 1.1115x; 1.1115x over previous
#include <cuda_runtime.h>

#define SEQ   96
#define PRED  16
#define HID   64
#define FEAT  7
#define BPB   4               // batches per block
#define NBLK  128             // 512/4 — one block per SM, single wave
#define NTHR  256
#define WIN   (SEQ + PRED)

typedef unsigned long long ull;

static __device__ __forceinline__ ull pack2(float a, float b){
    ull r; asm("mov.b64 %0, {%1, %2};" : "=l"(r) : "f"(a), "f"(b)); return r;
}
static __device__ __forceinline__ void unpack2(ull v, float &a, float &b){
    asm("mov.b64 {%0, %1}, %2;" : "=f"(a), "=f"(b) : "l"(v));
}
// d = a*b + d, packed f32x2 (Blackwell FFMA2), exact fp32 per lane
static __device__ __forceinline__ void ffma2(ull &d, ull a, ull b){
    asm("fma.rn.f32x2 %0, %1, %2, %0;" : "+l"(d) : "l"(a), "l"(b));
}

static __device__ __forceinline__ float sigmoid_fast(float x){
    float e = __expf(-x);
    return __fdividef(1.0f, 1.0f + e);
}
static __device__ __forceinline__ float tanhf_fast(float x){
    float e = __expf(-2.0f * x);
    return __fdividef(2.0f, 1.0f + e) - 1.0f;
}

__global__ void __launch_bounds__(NTHR, 1)
lstm_ar_kernel(const float* __restrict__ x,
               const float* __restrict__ W_ih,
               const float* __restrict__ W_hh,
               const float* __restrict__ b_ih,
               const float* __restrict__ b_hh,
               const float* __restrict__ fc_W,
               const float* __restrict__ fc_b,
               float* __restrict__ out)
{
    // sliding input window: [t][feat][b], b in [0,4)
    __shared__ float sh_xw[WIN * FEAT * BPB];
    // hidden state, double-buffered, batch-major: [buf][b][u]
    __shared__ float h_sh[2][BPB][HID];
    __shared__ float sh_fcW[FEAT * HID];
    __shared__ float sh_fcb[FEAT];

    const int tid = threadIdx.x;            // 0..255
    const int bp  = tid >> 7;               // batch pair: batches (2bp, 2bp+1)
    const int gp  = tid & 1;                // 0: rows i,f   1: rows g,o
    const int u   = (tid >> 1) & 63;        // hidden unit
    const int rA  = gp * 128 + u;           // i-row (gp0) / g-row (gp1)
    const int rB  = gp * 128 + 64 + u;      // f-row (gp0) / o-row (gp1)
    const int bO  = 2 * bp + gp;            // batch whose cell state this thread owns
    const int b0  = blockIdx.x * BPB;

    // ---------------- one-time init ----------------
    for (int i = tid; i < SEQ * FEAT * BPB; i += NTHR){
        int b = i & 3;
        int q = i >> 2;
        int f = q % FEAT;
        int t = q / FEAT;
        sh_xw[(t * FEAT + f) * BPB + b] =
            x[(size_t)(b0 + b) * SEQ * FEAT + t * FEAT + f];
    }
    for (int i = tid; i < FEAT * HID; i += NTHR) sh_fcW[i] = fc_W[i];
    if (tid < FEAT) sh_fcb[tid] = fc_b[tid];
    {
        float* hz = &h_sh[0][0][0];
        for (int i = tid; i < 2 * BPB * HID; i += NTHR) hz[i] = 0.0f;
    }

    // W_hh rows rA, rB as natural column-pairs: 64 u64 = 128 regs
    ull whhA[HID / 2], whhB[HID / 2];
    {
        const ull* wa = reinterpret_cast<const ull*>(W_hh + (size_t)rA * HID);
        const ull* wb = reinterpret_cast<const ull*>(W_hh + (size_t)rB * HID);
        #pragma unroll
        for (int c = 0; c < HID / 2; c++){ whhA[c] = wa[c]; whhB[c] = wb[c]; }
    }
    // W_ih rows, splatted for batch-pair f32x2 x-projection
    ull wihA2[FEAT], wihB2[FEAT];
    #pragma unroll
    for (int f = 0; f < FEAT; f++){
        float wa = W_ih[rA * FEAT + f];
        float wb = W_ih[rB * FEAT + f];
        wihA2[f] = pack2(wa, wa);
        wihB2[f] = pack2(wb, wb);
    }
    const ull seedA = pack2(b_ih[rA] + b_hh[rA], 0.0f);
    const ull seedB = pack2(b_ih[rB] + b_hh[rB], 0.0f);

    float c_reg = 0.0f;        // cell state of (batch bO, unit u)
    int p = 0;

    __syncthreads();

    // ---------------- 16 AR iterations x 96 recurrent steps ----------------
    for (int k = 0; k < PRED; k++){
        for (int t = 0; t < SEQ; t++){
            // ---- 4 dots: rows (rA,rB) x batches (2bp, 2bp+1) ----
            ull aA0 = seedA, aA1 = seedA;       // row A, batch even / odd
            ull aB0 = seedB, aB1 = seedB;       // row B
            const ulonglong2* hE =
                reinterpret_cast<const ulonglong2*>(&h_sh[p][2*bp    ][0]);
            const ulonglong2* hO =
                reinterpret_cast<const ulonglong2*>(&h_sh[p][2*bp + 1][0]);
            #pragma unroll
            for (int c = 0; c < 16; c++){
                ulonglong2 u0 = hE[c];          // cols 4c..4c+3, batch even (broadcast)
                ulonglong2 u1 = hO[c];          // batch odd
                ffma2(aA0, u0.x, whhA[2*c]);
                ffma2(aA0, u0.y, whhA[2*c+1]);
                ffma2(aB0, u0.x, whhB[2*c]);
                ffma2(aB0, u0.y, whhB[2*c+1]);
                ffma2(aA1, u1.x, whhA[2*c]);
                ffma2(aA1, u1.y, whhA[2*c+1]);
                ffma2(aB1, u1.x, whhB[2*c]);
                ffma2(aB1, u1.y, whhB[2*c+1]);
            }
            // x-projection packed over the batch pair
            ull xA = pack2(0.f, 0.f), xB = xA;
            {
                const float* xrow = &sh_xw[(k + t) * FEAT * BPB + 2 * bp];
                #pragma unroll
                for (int f = 0; f < FEAT; f++){
                    ull xx = *reinterpret_cast<const ull*>(xrow + f * BPB);
                    ffma2(xA, xx, wihA2[f]);
                    ffma2(xB, xx, wihB2[f]);
                }
            }
            float xa0, xa1, xb0, xb1, e, o;
            unpack2(xA, xa0, xa1);
            unpack2(xB, xb0, xb1);
            float vA0, vA1, vB0, vB1;
            unpack2(aA0, e, o); vA0 = (e + o) + xa0;   // rowA, batch even
            unpack2(aA1, e, o); vA1 = (e + o) + xa1;   // rowA, batch odd
            unpack2(aB0, e, o); vB0 = (e + o) + xb0;   // rowB, batch even
            unpack2(aB1, e, o); vB1 = (e + o) + xb1;   // rowB, batch odd

            // ---- pair exchange: 2 shfl.xor with lane^1 (gp partner) ----
            // gp0 owns batch even -> needs (g,o) even; sends (i,f) odd.
            // gp1 owns batch odd  -> needs (i,f) odd;  sends (g,o) even.
            float sA = gp ? vA0 : vA1;
            float sB = gp ? vB0 : vB1;
            float rAv = __shfl_xor_sync(0xffffffffu, sA, 1);
            float rBv = __shfl_xor_sync(0xffffffffu, sB, 1);
            float pi = gp ? rAv : vA0;
            float pf = gp ? rBv : vB0;
            float pg = gp ? vA1 : rAv;
            float po = gp ? vB1 : rBv;

            // ---- activations + cell update for (bO, u) ----
            float gi = sigmoid_fast(pi);
            float gf = sigmoid_fast(pf);
            float gg = tanhf_fast(pg);
            float go = sigmoid_fast(po);
            c_reg = fmaf(gf, c_reg, gi * gg);
            h_sh[p ^ 1][bO][u] = go * tanhf_fast(c_reg);

            __syncthreads();                 // single barrier per step
            p ^= 1;
        }

        // ---- fc head: pred = h @ fc_W^T + fc_b; append to window; emit ----
        if (tid < FEAT * BPB){
            int b  = tid / FEAT;
            int o2 = tid - b * FEAT;
            float acc = sh_fcb[o2];
            #pragma unroll
            for (int jj = 0; jj < HID; jj++)
                acc += h_sh[p][b][jj] * sh_fcW[o2 * HID + jj];
            out[(size_t)(b0 + b) * PRED * FEAT + k * FEAT + o2] = acc;
            sh_xw[((SEQ + k) * FEAT + o2) * BPB + b] = acc;
        }
        __syncthreads();
    }
}

extern "C" void kernel_launch(void* const* d_in, const int* in_sizes, int n_in,
                              void* d_out, int out_size)
{
    const float* x    = (const float*)d_in[0];
    const float* W_ih = (const float*)d_in[1];
    const float* W_hh = (const float*)d_in[2];
    const float* b_ih = (const float*)d_in[3];
    const float* b_hh = (const float*)d_in[4];
    const float* fc_W = (const float*)d_in[5];
    const float* fc_b = (const float*)d_in[6];
    float* out = (float*)d_out;

    lstm_ar_kernel<<<NBLK, NTHR>>>(x, W_ih, W_hh, b_ih, b_hh, fc_W, fc_b, out);
}